// round 1
// baseline (speedup 1.0000x reference)
#include <cuda_runtime.h>
#include <cuda_fp16.h>

// Problem constants
constexpr int BB = 256;   // batch
constexpr int KK = 8;     // in_size
constexpr int II = 1152;  // in_node_num
constexpr int NN = 10;    // num_node
constexpr int OO = 16;    // node_size
constexpr int PLANE = BB * OO;             // 4096 (per (i,n) plane, halves)
constexpr int UHAT_ELEMS = II * NN * BB * OO; // 47,185,920

// Static device scratch (allocation-free)
__device__ __half g_uhat[UHAT_ELEMS];          // ~94.4 MB, layout [i][n][b][o]
__device__ float  g_xt[II * BB * KK];          // xt[i][b][k] = x[b][k][i]
__device__ float  g_bij[II * NN];
__device__ float  g_c[II * NN];
__device__ float  g_spart[4][BB * NN * OO];    // partial s over i-chunks
__device__ float  g_v[BB * NN * OO];

// ---------------------------------------------------------------------------
// K0: transpose x (B,K,I) viewed as 2048 x 1152  ->  xt 1152 x 2048
__global__ __launch_bounds__(256) void k_transpose(const float* __restrict__ x) {
    __shared__ float tile[32][33];
    int tx = threadIdx.x, ty = threadIdx.y;
    int cbase = blockIdx.x * 32;   // i
    int rbase = blockIdx.y * 32;   // bk
#pragma unroll
    for (int j = 0; j < 32; j += 8)
        tile[ty + j][tx] = x[(size_t)(rbase + ty + j) * II + (cbase + tx)];
    __syncthreads();
#pragma unroll
    for (int j = 0; j < 32; j += 8)
        g_xt[(size_t)(cbase + ty + j) * (BB * KK) + (rbase + tx)] = tile[tx][ty + j];
}

// zero the routing logits each launch (determinism across graph replays)
__global__ void k_zero_b() {
    int t = blockIdx.x * 256 + threadIdx.x;
    if (t < II * NN) g_bij[t] = 0.0f;
}

// ---------------------------------------------------------------------------
// K1: build u_hat[i][n][b][o] = sum_k 0.03*W[i,n,o,k] * xt[i][b][k]  (fp16 out)
// One block per i. thread t == b, x in registers, W broadcast from smem.
__global__ __launch_bounds__(256) void k_build(const float* __restrict__ W) {
    int i = blockIdx.x;
    int t = threadIdx.x;                    // = b
    __shared__ float  sW[NN * OO * KK];     // 1280 floats (scaled by 0.03)
    __shared__ __half sOut[BB * 18];        // padded rows (18 halves) -> no bank conflicts

    const float* Wi = W + (size_t)i * NN * OO * KK;
    for (int j = t; j < NN * OO * KK; j += 256) sW[j] = 0.03f * Wi[j];

    const float4* xp = reinterpret_cast<const float4*>(g_xt + ((size_t)i * BB + t) * KK);
    float4 xa = xp[0];
    float4 xc = xp[1];
    __syncthreads();

    for (int n = 0; n < NN; n++) {
#pragma unroll
        for (int o2 = 0; o2 < 8; o2++) {
            const float4* wp = reinterpret_cast<const float4*>(sW + (n * OO + 2 * o2) * KK);
            float4 w0 = wp[0], w1 = wp[1], w2 = wp[2], w3 = wp[3];
            float d0 = w0.x * xa.x + w0.y * xa.y + w0.z * xa.z + w0.w * xa.w
                     + w1.x * xc.x + w1.y * xc.y + w1.z * xc.z + w1.w * xc.w;
            float d1 = w2.x * xa.x + w2.y * xa.y + w2.z * xa.z + w2.w * xa.w
                     + w3.x * xc.x + w3.y * xc.y + w3.z * xc.z + w3.w * xc.w;
            *reinterpret_cast<__half2*>(sOut + t * 18 + 2 * o2) = __floats2half2_rn(d0, d1);
        }
        __syncthreads();
        // flush: depad 256x16 halves -> global, coalesced half2
        __half2* dst = reinterpret_cast<__half2*>(g_uhat + ((size_t)i * NN + n) * PLANE);
#pragma unroll
        for (int p = 0; p < 8; p++) {
            int j = p * 256 + t;            // 0..2047 half2 slots
            int b = j >> 3, oo2 = j & 7;
            dst[j] = *reinterpret_cast<const __half2*>(sOut + b * 18 + 2 * oo2);
        }
        __syncthreads();
    }
}

// ---------------------------------------------------------------------------
// K2: c = softmax(b_ij, axis=n)
__global__ void k_softmax() {
    int i = blockIdx.x * 256 + threadIdx.x;
    if (i >= II) return;
    float bv[NN];
    float m = -1e30f;
#pragma unroll
    for (int n = 0; n < NN; n++) { bv[n] = g_bij[i * NN + n]; m = fmaxf(m, bv[n]); }
    float sum = 0.0f;
#pragma unroll
    for (int n = 0; n < NN; n++) { bv[n] = __expf(bv[n] - m); sum += bv[n]; }
    float inv = 1.0f / sum;
#pragma unroll
    for (int n = 0; n < NN; n++) g_c[i * NN + n] = bv[n] * inv;
}

// ---------------------------------------------------------------------------
// K3: s partials. grid = 10(n) * 8(b-chunk) * 4(i-chunk) = 320 blocks, 256 thr.
// s_part[ic][b][n][o] = sum_{i in chunk} c[i,n] * u_hat[i][n][b][o]
__global__ __launch_bounds__(256) void k_spass() {
    int bx = blockIdx.x;
    int n  = bx / 32;
    int r  = bx % 32;
    int b0 = (r >> 2) * 32;
    int i0 = (r & 3) * 288;
    int t  = threadIdx.x;
    int bl = t >> 3, o2 = t & 7;

    __shared__ float sc[288];
    for (int j = t; j < 288; j += 256) sc[j] = g_c[(i0 + j) * NN + n];
    __syncthreads();

    const __half2* p = reinterpret_cast<const __half2*>(g_uhat)
                     + ((size_t)((i0 * NN + n) * BB + b0 + bl)) * (OO / 2) + o2;
    const int stride = NN * BB * (OO / 2);  // one i step, in half2
    float a0 = 0.0f, a1 = 0.0f;
#pragma unroll 4
    for (int ii = 0; ii < 288; ii++) {
        float2 u = __half22float2(*p);
        float cc = sc[ii];
        a0 += cc * u.x;
        a1 += cc * u.y;
        p += stride;
    }
    float2* sp = reinterpret_cast<float2*>(&g_spart[r & 3][((b0 + bl) * NN + n) * OO]) + o2;
    *sp = make_float2(a0, a1);
}

// ---------------------------------------------------------------------------
// K4: reduce 4 partials, squash over o, write v (and output). grid 160 x 256.
__global__ __launch_bounds__(256) void k_squash(float* __restrict__ out) {
    int w = threadIdx.x >> 5, lane = threadIdx.x & 31;
    int g = lane >> 4, o = lane & 15;
    int pidx = blockIdx.x * 16 + w * 2 + g;   // (b,n) pair, 0..2559
    int b = pidx / NN, n = pidx % NN;
    int idx = (b * NN + n) * OO + o;
    float s = g_spart[0][idx] + g_spart[1][idx] + g_spart[2][idx] + g_spart[3][idx];
    float m = s * s;
    m += __shfl_xor_sync(0xffffffffu, m, 8);
    m += __shfl_xor_sync(0xffffffffu, m, 4);
    m += __shfl_xor_sync(0xffffffffu, m, 2);
    m += __shfl_xor_sync(0xffffffffu, m, 1);
    float mag = sqrtf(m);
    float v = s * mag / (1.0f + m);
    g_v[idx] = v;
    out[idx] = v;
}

// ---------------------------------------------------------------------------
// K5: u_vj[i,n] = (1/B) sum_{b,o} u_hat[i][n][b][o] * v[b,n,o]; b_ij += u_vj
// grid = 144(i-chunk of 8) * 10(n) = 1440 blocks, 256 thr.
__global__ __launch_bounds__(256) void k_uv() {
    int bx = blockIdx.x;
    int n  = bx % NN;
    int i0 = (bx / NN) * 8;
    int t  = threadIdx.x;

    __shared__ float sv[PLANE];   // v[:, n, :]  (4096 floats)
    __shared__ float sred[8];
    for (int j = t; j < PLANE; j += 256) {
        int b = j >> 4, o = j & 15;
        sv[j] = g_v[(b * NN + n) * OO + o];
    }
    __syncthreads();

    for (int q = 0; q < 8; q++) {
        int i = i0 + q;
        const __half2* p = reinterpret_cast<const __half2*>(g_uhat)
                         + ((size_t)i * NN + n) * (PLANE / 2);
        const float2* vv = reinterpret_cast<const float2*>(sv);
        float acc = 0.0f;
#pragma unroll
        for (int pp = 0; pp < 8; pp++) {
            int j2 = pp * 256 + t;
            float2 u = __half22float2(p[j2]);
            float2 v2 = vv[j2];
            acc += u.x * v2.x + u.y * v2.y;
        }
#pragma unroll
        for (int sft = 16; sft > 0; sft >>= 1)
            acc += __shfl_xor_sync(0xffffffffu, acc, sft);
        if ((t & 31) == 0) sred[t >> 5] = acc;
        __syncthreads();
        if (t == 0) {
            float a = 0.0f;
#pragma unroll
            for (int ww = 0; ww < 8; ww++) a += sred[ww];
            g_bij[i * NN + n] += a * (1.0f / BB);
        }
        __syncthreads();
    }
}

// ---------------------------------------------------------------------------
extern "C" void kernel_launch(void* const* d_in, const int* in_sizes, int n_in,
                              void* d_out, int out_size) {
    const float* x = (const float*)d_in[0];   // (256, 8, 1152) fp32
    const float* W = (const float*)d_in[1];   // (1, 1152, 10, 16, 8) fp32
    float* out = (float*)d_out;               // (256, 10, 16, 1) fp32

    k_transpose<<<dim3(II / 32, (BB * KK) / 32), dim3(32, 8)>>>(x);
    k_zero_b<<<(II * NN + 255) / 256, 256>>>();
    k_build<<<II, 256>>>(W);

    for (int it = 0; it < 3; it++) {
        k_softmax<<<(II + 255) / 256, 256>>>();
        k_spass<<<320, 256>>>();
        k_squash<<<160, 256>>>(out);
        if (it < 2) k_uv<<<1440, 256>>>();
    }
}

// round 3
// speedup vs baseline: 1.7591x; 1.7591x over previous
#include <cuda_runtime.h>
#include <cuda_fp16.h>

// Problem constants
constexpr int BB = 256;   // batch
constexpr int KK = 8;     // in_size
constexpr int II = 1152;  // in_node_num
constexpr int NN = 10;    // num_node
constexpr int OO = 16;    // node_size
constexpr int PLANE = BB * OO;                  // 4096 halves per (i,n)
constexpr int UHAT_ELEMS = II * NN * BB * OO;   // 47,185,920
constexpr int ICH_S = 72;                       // i-chunk for s-pass
constexpr int NCH_S = II / ICH_S;               // 16 partial buffers
constexpr int ICH_F = 8;                        // i-chunk for fused uv pass

// Static device scratch (allocation-free)
__device__ __half g_uhat[UHAT_ELEMS];           // ~94.4 MB, layout [i][n][b][o]
__device__ float  g_xt[II * BB * KK];           // xt[i][b][k]
__device__ float  g_bij[II * NN];
__device__ float  g_c[II * NN];
__device__ float  g_spart[NCH_S][BB * NN * OO]; // partial s over i-chunks
__device__ float  g_v[BB * NN * OO];

// packed f32x2 FMA (sm_100+): full fp32 precision, 2x FFMA throughput
#define FMA_F32X2(out, a, b, c) \
    asm("fma.rn.f32x2 %0, %1, %2, %3;" : "=l"(out) : "l"(a), "l"(b), "l"(c))

__device__ __forceinline__ unsigned long long packf2(float lo, float hi) {
    unsigned long long r;
    asm("mov.b64 %0, {%1, %2};" : "=l"(r) : "f"(lo), "f"(hi));
    return r;
}
__device__ __forceinline__ float2 unpackf2(unsigned long long p) {
    float2 r;
    asm("mov.b64 {%0, %1}, %2;" : "=f"(r.x), "=f"(r.y) : "l"(p));
    return r;
}

// ---------------------------------------------------------------------------
// K0: transpose x (B,K,I) viewed as 2048 x 1152  ->  xt 1152 x 2048
__global__ __launch_bounds__(256) void k_transpose(const float* __restrict__ x) {
    __shared__ float tile[32][33];
    int tx = threadIdx.x, ty = threadIdx.y;
    int cbase = blockIdx.x * 32;   // i
    int rbase = blockIdx.y * 32;   // bk
#pragma unroll
    for (int j = 0; j < 32; j += 8)
        tile[ty + j][tx] = x[(size_t)(rbase + ty + j) * II + (cbase + tx)];
    __syncthreads();
#pragma unroll
    for (int j = 0; j < 32; j += 8)
        g_xt[(size_t)(cbase + ty + j) * (BB * KK) + (rbase + tx)] = tile[tx][ty + j];
}

// ---------------------------------------------------------------------------
// K1: build u_hat[i][n][b][o] = sum_k 0.03*W[i,n,o,k] * xt[i][b][k]  (fp16)
// One block per i, thread t == b. Packed f32x2 FMAs, direct coalesced stores.
__global__ __launch_bounds__(256) void k_build(const float* __restrict__ W) {
    int i = blockIdx.x;
    int t = threadIdx.x;                         // = b
    __shared__ unsigned long long sWp[NN * 8 * KK];  // 640 packed pairs (5KB)

    const float* Wi = W + (size_t)i * NN * OO * KK;
    for (int p = t; p < NN * 8 * KK; p += 256) {
        int n = p >> 6, o2 = (p >> 3) & 7, k = p & 7;
        float w0 = 0.03f * Wi[(n * OO + 2 * o2) * KK + k];
        float w1 = 0.03f * Wi[(n * OO + 2 * o2 + 1) * KK + k];
        sWp[p] = packf2(w0, w1);
    }

    // x broadcast pairs {x_k, x_k}
    const float4* xp = reinterpret_cast<const float4*>(g_xt + ((size_t)i * BB + t) * KK);
    float4 xa = xp[0], xc = xp[1];
    unsigned long long xb[8];
    xb[0] = packf2(xa.x, xa.x); xb[1] = packf2(xa.y, xa.y);
    xb[2] = packf2(xa.z, xa.z); xb[3] = packf2(xa.w, xa.w);
    xb[4] = packf2(xc.x, xc.x); xb[5] = packf2(xc.y, xc.y);
    xb[6] = packf2(xc.z, xc.z); xb[7] = packf2(xc.w, xc.w);
    __syncthreads();

    for (int n = 0; n < NN; n++) {
        __half2 oh[8];
#pragma unroll
        for (int o2 = 0; o2 < 8; o2++) {
            unsigned long long acc = 0ull;
            const unsigned long long* wp = &sWp[(n * 8 + o2) * KK];
#pragma unroll
            for (int k = 0; k < KK; k++) FMA_F32X2(acc, wp[k], xb[k], acc);
            float2 d = unpackf2(acc);
            oh[o2] = __floats2half2_rn(d.x, d.y);
        }
        uint4* dst = reinterpret_cast<uint4*>(g_uhat + (((size_t)i * NN + n) * BB + t) * OO);
        dst[0] = *reinterpret_cast<const uint4*>(&oh[0]);
        dst[1] = *reinterpret_cast<const uint4*>(&oh[4]);
    }
}

// ---------------------------------------------------------------------------
// K2: s partials.  grid = n(10) x ic(16) x bh(2) = 320 blocks, 256 threads.
// thread owns (b, o-half): one uint4 (8 halves) per i step.
__global__ __launch_bounds__(256) void k_spass(int use_const) {
    int bx = blockIdx.x;
    int n  = bx >> 5;
    int ic = (bx >> 1) & 15;
    int bh = bx & 1;
    int i0 = ic * ICH_S;
    int t  = threadIdx.x;
    int b  = bh * 128 + (t >> 1);
    int oh = t & 1;

    __shared__ float sc[ICH_S];
    if (t < ICH_S) sc[t] = use_const ? 0.1f : g_c[(i0 + t) * NN + n];
    __syncthreads();

    const uint4* base = reinterpret_cast<const uint4*>(g_uhat)
                      + (((size_t)(i0 * NN + n) * BB + b) * 2 + oh);
    const size_t stride = (size_t)NN * BB * 2;   // one i step, in uint4

    float a[8];
#pragma unroll
    for (int j = 0; j < 8; j++) a[j] = 0.0f;

#pragma unroll 8
    for (int ii = 0; ii < ICH_S; ii++) {
        uint4 u = base[ii * stride];
        float cc = sc[ii];
        const __half2* h = reinterpret_cast<const __half2*>(&u);
#pragma unroll
        for (int q = 0; q < 4; q++) {
            float2 f = __half22float2(h[q]);
            a[2 * q]     += cc * f.x;
            a[2 * q + 1] += cc * f.y;
        }
    }
    float4* sp = reinterpret_cast<float4*>(&g_spart[ic][(b * NN + n) * OO + oh * 8]);
    sp[0] = make_float4(a[0], a[1], a[2], a[3]);
    sp[1] = make_float4(a[4], a[5], a[6], a[7]);
}

// ---------------------------------------------------------------------------
// K3: reduce partials, squash over o, write v (and out). grid 160 x 256.
__global__ __launch_bounds__(256) void k_squash(float* __restrict__ out) {
    int w = threadIdx.x >> 5, lane = threadIdx.x & 31;
    int g = lane >> 4, o = lane & 15;
    int pidx = blockIdx.x * 16 + w * 2 + g;   // (b,n) pair, 0..2559
    int b = pidx / NN, n = pidx % NN;
    int idx = (b * NN + n) * OO + o;
    float s = 0.0f;
#pragma unroll
    for (int p = 0; p < NCH_S; p++) s += g_spart[p][idx];
    float m = s * s;
    m += __shfl_xor_sync(0xffffffffu, m, 8);
    m += __shfl_xor_sync(0xffffffffu, m, 4);
    m += __shfl_xor_sync(0xffffffffu, m, 2);
    m += __shfl_xor_sync(0xffffffffu, m, 1);
    float mag = sqrtf(m);
    float v = s * mag / (1.0f + m);
    g_v[idx] = v;
    out[idx] = v;
}

// ---------------------------------------------------------------------------
// K4: fused agreement + routing update:
//   uv[i,n] = sum_{b,o} u_hat[i,n,b,o]*v[b,n,o];  b += uv/B;  c = softmax_n(b)
// grid = 144 (i-chunks of 8), block 320 = 10 warps (warp w == n).
// Each lane owns 16 fixed uint4 slots of the 512-uint4 plane (FULL batch).
__global__ __launch_bounds__(320) void k_fused(int first) {
    int i0 = blockIdx.x * ICH_F;
    int w  = threadIdx.x >> 5;     // n
    int l  = threadIdx.x & 31;

    // preload v at this lane's fixed (b,o) slots: 128 registers (full plane)
    float vr[128];
#pragma unroll
    for (int s = 0; s < 16; s++) {
        int j = l + 32 * s;               // uint4 slot 0..511
        int b = j >> 1, o0 = (j & 1) * 8;
        const float4* vp = reinterpret_cast<const float4*>(&g_v[(b * NN + w) * OO + o0]);
        float4 v0 = vp[0], v1 = vp[1];
        vr[s * 8 + 0] = v0.x; vr[s * 8 + 1] = v0.y; vr[s * 8 + 2] = v0.z; vr[s * 8 + 3] = v0.w;
        vr[s * 8 + 4] = v1.x; vr[s * 8 + 5] = v1.y; vr[s * 8 + 6] = v1.z; vr[s * 8 + 7] = v1.w;
    }

    __shared__ float suv[ICH_F][NN];

    for (int q = 0; q < ICH_F; q++) {
        int i = i0 + q;
        const uint4* base = reinterpret_cast<const uint4*>(g_uhat)
                          + (size_t)(i * NN + w) * (PLANE / 8);
        float acc = 0.0f;
#pragma unroll
        for (int g2 = 0; g2 < 2; g2++) {
            uint4 u[8];
#pragma unroll
            for (int s = 0; s < 8; s++) u[s] = base[l + 32 * (g2 * 8 + s)];
#pragma unroll
            for (int s = 0; s < 8; s++) {
                const __half2* h = reinterpret_cast<const __half2*>(&u[s]);
                int vb = (g2 * 8 + s) * 8;
#pragma unroll
                for (int p = 0; p < 4; p++) {
                    float2 f = __half22float2(h[p]);
                    acc += f.x * vr[vb + 2 * p] + f.y * vr[vb + 2 * p + 1];
                }
            }
        }
#pragma unroll
        for (int sft = 16; sft > 0; sft >>= 1)
            acc += __shfl_xor_sync(0xffffffffu, acc, sft);
        if (l == 0) suv[q][w] = acc;
    }
    __syncthreads();

    if (threadIdx.x < ICH_F) {
        int i = i0 + threadIdx.x;
        float bv[NN];
        float m = -1e30f;
#pragma unroll
        for (int n = 0; n < NN; n++) {
            float bprev = first ? 0.0f : g_bij[i * NN + n];
            bv[n] = bprev + suv[threadIdx.x][n] * (1.0f / BB);
            m = fmaxf(m, bv[n]);
        }
        if (first) {
#pragma unroll
            for (int n = 0; n < NN; n++) g_bij[i * NN + n] = bv[n];
        }
        float sum = 0.0f;
#pragma unroll
        for (int n = 0; n < NN; n++) { bv[n] = __expf(bv[n] - m); sum += bv[n]; }
        float inv = 1.0f / sum;
#pragma unroll
        for (int n = 0; n < NN; n++) g_c[i * NN + n] = bv[n] * inv;
    }
}

// ---------------------------------------------------------------------------
extern "C" void kernel_launch(void* const* d_in, const int* in_sizes, int n_in,
                              void* d_out, int out_size) {
    const float* x = (const float*)d_in[0];   // (256, 8, 1152) fp32
    const float* W = (const float*)d_in[1];   // (1, 1152, 10, 16, 8) fp32
    float* out = (float*)d_out;               // (256, 10, 16, 1) fp32

    k_transpose<<<dim3(II / 32, (BB * KK) / 32), dim3(32, 8)>>>(x);
    k_build<<<II, 256>>>(W);

    // iter 1: c is uniform 0.1 (softmax of zeros)
    k_spass<<<320, 256>>>(1);
    k_squash<<<160, 256>>>(out);
    // iter 2
    k_fused<<<II / ICH_F, 320>>>(1);
    k_spass<<<320, 256>>>(0);
    k_squash<<<160, 256>>>(out);
    // iter 3
    k_fused<<<II / ICH_F, 320>>>(0);
    k_spass<<<320, 256>>>(0);
    k_squash<<<160, 256>>>(out);
}